// round 5
// baseline (speedup 1.0000x reference)
#include <cuda_runtime.h>
#include <cuda_bf16.h>

// HeadDetectorLoss: persistent double-buffered streaming reduction.
//   inputs: prediction (N,6) f32, target_class (N,) i32, target_box (N,4) f32
//   output: scalar = mean(lse - l[tc]) + 10 * sum_masked(mse) / (1e-6 + count)
//
// R1/R3/R4 all plateaued at 5.4-5.6 TB/s despite very different shapes; the
// common factor is bursty demand (load phase -> dead compute phase). Here each
// block loops over tiles with TWO smem buffers: the cp.async prefetch of tile
// i+1 is issued BEFORE waiting on tile i, so every SM keeps a full tile load
// in flight at all times. All global loads remain perfectly coalesced 16B
// cp.async.cg (L1 bypass).

#define NTHREADS   256
#define TILE_ROWS  512
#define PRED_F4    (TILE_ROWS * 3 / 2)   // 768  x 16B = 12288 B
#define BOX_F4     (TILE_ROWS)           // 512  x 16B =  8192 B
#define CLS_I4     (TILE_ROWS / 4)       // 128  x 16B =  2048 B
#define NBLOCKS    1480                  // ~5 resident blocks per SM (148 SMs)

__device__ double       g_nll  = 0.0;
__device__ double       g_box  = 0.0;
__device__ double       g_msk  = 0.0;
__device__ unsigned int g_done = 0u;

__device__ __forceinline__ void cp16(void* smem_dst, const void* gmem_src)
{
    unsigned s = (unsigned)__cvta_generic_to_shared(smem_dst);
    asm volatile("cp.async.cg.shared.global [%0], [%1], 16;\n"
                 :: "r"(s), "l"(gmem_src) : "memory");
}

__device__ __forceinline__ void do_row(float l0, float l1,
                                       float p0, float p1, float p2, float p3,
                                       float t0, float t1, float t2, float t3,
                                       int tc, float& nll, float& box, float& msk)
{
    const float hi = fmaxf(l0, l1), lo = fminf(l0, l1);
    const float lse = hi + __logf(1.0f + __expf(lo - hi));
    nll += lse - (tc == 0 ? l0 : l1);
    if (tc != 0) {
        const float d0 = p0 - t0, d1 = p1 - t1, d2 = p2 - t2, d3 = p3 - t3;
        box += 0.25f * ((d0 * d0 + d1 * d1) + (d2 * d2 + d3 * d3));
        msk += 1.f;
    }
}

__global__ __launch_bounds__(NTHREADS)
void head_loss_kernel(const float* __restrict__ pred,
                      const int*   __restrict__ tcls,
                      const float* __restrict__ tbox,
                      float*       __restrict__ out,
                      int n)
{
    __shared__ float4 s_pred[2][PRED_F4];
    __shared__ float4 s_box [2][BOX_F4];
    __shared__ int4   s_cls [2][CLS_I4];

    const int tid = threadIdx.x;
    const int ntiles = (n + TILE_ROWS - 1) / TILE_ROWS;

    const float4* gpred = (const float4*)pred;
    const float4* gbox  = (const float4*)tbox;
    const int4*   gcls  = (const int4*)tcls;

    // tile loader: all accesses lane-coalesced at 16B
    auto load_tile = [&](int tile, int buf) {
        const long base = (long)tile * TILE_ROWS;
        const int  rows = (int)min((long)TILE_ROWS, (long)n - base);
        const int  pf4  = (3 * rows + 1) >> 1;
        const int  bf4  = rows;
        const int  ci4  = (rows + 3) >> 2;
        const float4* gp = gpred + (base * 3 >> 1);
        const float4* gb = gbox + base;
        const int4*   gc = gcls + (base >> 2);
        #pragma unroll
        for (int k = 0; k < PRED_F4 / NTHREADS; k++) {
            const int i = tid + k * NTHREADS;
            if (i < pf4) cp16(&s_pred[buf][i], &gp[i]);
        }
        #pragma unroll
        for (int k = 0; k < BOX_F4 / NTHREADS; k++) {
            const int i = tid + k * NTHREADS;
            if (i < bf4) cp16(&s_box[buf][i], &gb[i]);
        }
        if (tid < ci4) cp16(&s_cls[buf][tid], &gc[tid]);
    };

    float nll = 0.f, box = 0.f, msk = 0.f;

    int tile = blockIdx.x;
    if (tile < ntiles) load_tile(tile, 0);
    asm volatile("cp.async.commit_group;\n" ::: "memory");

    int buf = 0;
    for (; tile < ntiles; tile += gridDim.x) {
        // prefetch next tile into the other buffer BEFORE consuming this one
        const int next = tile + gridDim.x;
        if (next < ntiles) load_tile(next, buf ^ 1);
        asm volatile("cp.async.commit_group;\n" ::: "memory");

        // wait until at most 1 group pending -> current tile's group is done
        asm volatile("cp.async.wait_group 1;\n" ::: "memory");
        __syncthreads();

        // ---- compute: 1 pair (2 rows) per thread ----
        {
            const long base = (long)tile * TILE_ROWS;
            const long r0   = base + 2 * tid;
            if (r0 < n) {
                const float4 a = s_pred[buf][3 * tid + 0];   // row0: l0 l1 b0 b1
                const float4 b = s_pred[buf][3 * tid + 1];   // row0: b2 b3 | row1: l0 l1
                const float4 c = s_pred[buf][3 * tid + 2];   // row1: b0 b1 b2 b3
                const float4 u = s_box[buf][2 * tid + 0];
                const float4 v = s_box[buf][2 * tid + 1];
                const int2  tc = reinterpret_cast<const int2*>(s_cls[buf])[tid];

                do_row(a.x, a.y, a.z, a.w, b.x, b.y, u.x, u.y, u.z, u.w, tc.x, nll, box, msk);
                if (r0 + 1 < n)
                    do_row(b.z, b.w, c.x, c.y, c.z, c.w, v.x, v.y, v.z, v.w, tc.y, nll, box, msk);
            }
        }
        __syncthreads();   // everyone done reading buf before it is refilled
        buf ^= 1;
    }

    // ---- intra-warp reduction ----
    #pragma unroll
    for (int o = 16; o > 0; o >>= 1) {
        nll += __shfl_down_sync(0xffffffffu, nll, o);
        box += __shfl_down_sync(0xffffffffu, box, o);
        msk += __shfl_down_sync(0xffffffffu, msk, o);
    }

    // ---- intra-block reduction ----
    __shared__ float r_nll[NTHREADS / 32], r_box[NTHREADS / 32], r_msk[NTHREADS / 32];
    const int lane = tid & 31, warp = tid >> 5;
    if (lane == 0) { r_nll[warp] = nll; r_box[warp] = box; r_msk[warp] = msk; }
    __syncthreads();

    if (tid == 0) {
        float tn = 0.f, tb = 0.f, tm = 0.f;
        #pragma unroll
        for (int w = 0; w < NTHREADS / 32; w++) { tn += r_nll[w]; tb += r_box[w]; tm += r_msk[w]; }

        atomicAdd(&g_nll, (double)tn);
        atomicAdd(&g_box, (double)tb);
        atomicAdd(&g_msk, (double)tm);
        __threadfence();
        const unsigned v = atomicAdd(&g_done, 1u);
        if (v == gridDim.x - 1) {
            __threadfence();
            const double sn = atomicAdd(&g_nll, 0.0);
            const double sb = atomicAdd(&g_box, 0.0);
            const double sm = atomicAdd(&g_msk, 0.0);
            out[0] = (float)(sn / (double)n + 10.0 * sb / (1e-6 + sm));
            g_nll = 0.0; g_box = 0.0; g_msk = 0.0; g_done = 0u;   // reset for next replay
        }
    }
}

extern "C" void kernel_launch(void* const* d_in, const int* in_sizes, int n_in,
                              void* d_out, int out_size)
{
    const float* pred = (const float*)d_in[0];
    const int*   tcls = (const int*)  d_in[1];
    const float* tbox = (const float*)d_in[2];
    float*       out  = (float*)d_out;
    const int n = in_sizes[1];   // N

    head_loss_kernel<<<NBLOCKS, NTHREADS>>>(pred, tcls, tbox, out, n);
}